// round 1
// baseline (speedup 1.0000x reference)
#include <cuda_runtime.h>
#include <cuda_bf16.h>
#include <math.h>

// Problem constants (fixed shapes)
#define NN    50000
#define EE    800000
#define ET    850000          // EE + NN self-loops
#define FIN   512
#define HEADS 4
#define HID   64
#define HO1   256             // HEADS*HID
#define NC    40
#define NEG_SLOPE 0.2f

// ---------------- device scratch (static, no allocations) ----------------
__device__ float g_h1 [(size_t)NN * HO1];   // x@W1
__device__ float g_h1p[(size_t)NN * HO1];   // relu(agg1 + b1)
__device__ float g_h2 [(size_t)NN * NC];    // h1p@W2
__device__ float g_as1[NN * HEADS];
__device__ float g_ad1[NN * HEADS];
__device__ float g_as2[NN];
__device__ float g_ad2[NN];
__device__ int   g_deg[NN];
__device__ int   g_rowptr[NN + 1];
__device__ int   g_cursor[NN];
__device__ int   g_col [ET];
__device__ float g_wcsr[ET];

// ---------------- CSR build ----------------
__global__ void k_deg_init() {
    int i = blockIdx.x * blockDim.x + threadIdx.x;
    if (i < NN) g_deg[i] = 1;   // self-loop
}

__global__ void k_count(const int* __restrict__ dst) {
    int e = blockIdx.x * blockDim.x + threadIdx.x;
    if (e < EE) atomicAdd(&g_deg[dst[e]], 1);
}

// single-block exclusive scan over g_deg -> g_rowptr (+ cursor copy)
__global__ void k_scan() {
    __shared__ int partial[1024];
    const int n = NN;
    const int chunk = (n + 1023) / 1024;
    int t = threadIdx.x;
    int beg = t * chunk;
    int end = beg + chunk; if (end > n) end = n;
    int s = 0;
    for (int i = beg; i < end && i < n; i++) s += g_deg[i];
    partial[t] = s;
    __syncthreads();
    // Hillis-Steele inclusive scan
    for (int off = 1; off < 1024; off <<= 1) {
        int v = (t >= off) ? partial[t - off] : 0;
        __syncthreads();
        partial[t] += v;
        __syncthreads();
    }
    int run = (t == 0) ? 0 : partial[t - 1];
    for (int i = beg; i < end && i < n; i++) {
        g_rowptr[i] = run;
        g_cursor[i] = run;
        run += g_deg[i];
    }
    if (t == 1023) g_rowptr[n] = partial[1023];
}

__global__ void k_scatter(const int* __restrict__ src, const int* __restrict__ dst,
                          const float* __restrict__ ew) {
    int e = blockIdx.x * blockDim.x + threadIdx.x;
    if (e < EE) {
        int d = dst[e];
        int pos = atomicAdd(&g_cursor[d], 1);
        g_col[pos]  = src[e];
        g_wcsr[pos] = ew[e];
    }
}

__global__ void k_selfloop() {
    int i = blockIdx.x * blockDim.x + threadIdx.x;
    if (i < NN) {
        int pos = atomicAdd(&g_cursor[i], 1);
        g_col[pos]  = i;
        g_wcsr[pos] = 1.0f;
    }
}

// ---------------- GEMM1: [NN,FIN] x [FIN,HO1] -> g_h1 ----------------
// 128x128x16 tiles, 256 threads, 8x8 per thread
__global__ __launch_bounds__(256) void k_gemm1(const float* __restrict__ A,
                                               const float* __restrict__ B) {
    const int M = NN, N = HO1, K = FIN;
    __shared__ float As[16][128];
    __shared__ float Bs[16][128];
    int tid = threadIdx.x;
    int tx = tid % 16, ty = tid / 16;
    int rowBase = blockIdx.y * 128;
    int colBase = blockIdx.x * 128;

    int aRow  = tid >> 2;          // 0..63
    int aCol4 = (tid & 3) * 4;     // 0,4,8,12
    int bRow  = tid >> 5;          // 0..7
    int bCol4 = (tid & 31) * 4;    // 0..124

    float acc[8][8];
#pragma unroll
    for (int i = 0; i < 8; i++)
#pragma unroll
        for (int j = 0; j < 8; j++) acc[i][j] = 0.0f;

    for (int k0 = 0; k0 < K; k0 += 16) {
#pragma unroll
        for (int i = 0; i < 2; i++) {
            int r = aRow + 64 * i;
            int grow = rowBase + r;
            float4 v = make_float4(0.f, 0.f, 0.f, 0.f);
            if (grow < M) v = *(const float4*)&A[(size_t)grow * K + k0 + aCol4];
            As[aCol4 + 0][r] = v.x;
            As[aCol4 + 1][r] = v.y;
            As[aCol4 + 2][r] = v.z;
            As[aCol4 + 3][r] = v.w;
        }
#pragma unroll
        for (int i = 0; i < 2; i++) {
            int r = bRow + 8 * i;
            *(float4*)&Bs[r][bCol4] = *(const float4*)&B[(size_t)(k0 + r) * N + colBase + bCol4];
        }
        __syncthreads();
#pragma unroll
        for (int kk = 0; kk < 16; kk++) {
            float a_reg[8], b_reg[8];
            *(float4*)&a_reg[0] = *(const float4*)&As[kk][ty * 8 + 0];
            *(float4*)&a_reg[4] = *(const float4*)&As[kk][ty * 8 + 4];
            *(float4*)&b_reg[0] = *(const float4*)&Bs[kk][tx * 8 + 0];
            *(float4*)&b_reg[4] = *(const float4*)&Bs[kk][tx * 8 + 4];
#pragma unroll
            for (int i = 0; i < 8; i++)
#pragma unroll
                for (int j = 0; j < 8; j++) acc[i][j] += a_reg[i] * b_reg[j];
        }
        __syncthreads();
    }
#pragma unroll
    for (int i = 0; i < 8; i++) {
        int grow = rowBase + ty * 8 + i;
        if (grow >= M) continue;
#pragma unroll
        for (int j = 0; j < 8; j += 4) {
            float4 v = make_float4(acc[i][j], acc[i][j + 1], acc[i][j + 2], acc[i][j + 3]);
            *(float4*)&g_h1[(size_t)grow * N + colBase + tx * 8 + j] = v;
        }
    }
}

// ---------------- alpha1: per (node, head) dot with a_src1 / a_dst1 ----------------
__global__ void k_alpha1(const float* __restrict__ a_s, const float* __restrict__ a_d) {
    int gw = (blockIdx.x * blockDim.x + threadIdx.x) >> 5;   // global warp id
    int lane = threadIdx.x & 31;
    if (gw >= NN * HEADS) return;
    int node = gw >> 2;
    int hd = gw & 3;
    const float* hrow = &g_h1[(size_t)node * HO1 + hd * HID];
    float2 hv  = *(const float2*)&hrow[lane * 2];
    float2 asv = *(const float2*)&a_s[hd * HID + lane * 2];
    float2 adv = *(const float2*)&a_d[hd * HID + lane * 2];
    float ps = hv.x * asv.x + hv.y * asv.y;
    float pd = hv.x * adv.x + hv.y * adv.y;
#pragma unroll
    for (int off = 16; off > 0; off >>= 1) {
        ps += __shfl_down_sync(0xffffffff, ps, off);
        pd += __shfl_down_sync(0xffffffff, pd, off);
    }
    if (lane == 0) {
        g_as1[gw] = ps;
        g_ad1[gw] = pd;
    }
}

// ---------------- aggregation layer 1 ----------------
// 64 threads per node (4 nodes / 256-thread block); thread t owns flat channels [4t,4t+4)
__global__ void k_agg1(const float* __restrict__ b1) {
    int node = blockIdx.x * 4 + (threadIdx.x >> 6);
    int t = threadIdx.x & 63;
    if (node >= NN) return;
    int hd = t >> 4;
    float ad = g_ad1[node * HEADS + hd];
    int beg = g_rowptr[node], end = g_rowptr[node + 1];

    float m = -INFINITY;
    for (int e = beg; e < end; e++) {
        int s = g_col[e];
        float v = g_as1[s * HEADS + hd] + ad;
        v = v > 0.f ? v : NEG_SLOPE * v;
        m = fmaxf(m, v);
    }
    float denom = 0.f;
    float4 acc = make_float4(0.f, 0.f, 0.f, 0.f);
    for (int e = beg; e < end; e++) {
        int s = g_col[e];
        float v = g_as1[s * HEADS + hd] + ad;
        v = v > 0.f ? v : NEG_SLOPE * v;
        float ex = __expf(v - m);
        denom += ex;
        float w = ex * g_wcsr[e];
        float4 hv = *(const float4*)&g_h1[(size_t)s * HO1 + 4 * t];
        acc.x += w * hv.x;
        acc.y += w * hv.y;
        acc.z += w * hv.z;
        acc.w += w * hv.w;
    }
    float inv = 1.0f / (denom + 1e-16f);
    float4 b = *(const float4*)&b1[4 * t];
    float4 o;
    o.x = fmaxf(acc.x * inv + b.x, 0.f);
    o.y = fmaxf(acc.y * inv + b.y, 0.f);
    o.z = fmaxf(acc.z * inv + b.z, 0.f);
    o.w = fmaxf(acc.w * inv + b.w, 0.f);
    *(float4*)&g_h1p[(size_t)node * HO1 + 4 * t] = o;
}

// ---------------- GEMM2: [NN,HO1] x [HO1,NC] -> g_h2 ----------------
// 8 rows per 256-thread block; W2 staged in smem
__global__ __launch_bounds__(256) void k_gemm2(const float* __restrict__ W2) {
    __shared__ float Ws[HO1 * NC];       // 40 KB
    __shared__ float rowbuf[8][HO1];     // 8 KB
    int t = threadIdx.x;
    for (int i = t; i < HO1 * NC; i += 256) Ws[i] = W2[i];
    int wid = t >> 5, lane = t & 31;
    int row = blockIdx.x * 8 + wid;
    __syncthreads();
    if (row < NN) {
#pragma unroll
        for (int i = 0; i < 2; i++)
            *(float4*)&rowbuf[wid][lane * 4 + i * 128] =
                *(const float4*)&g_h1p[(size_t)row * HO1 + lane * 4 + i * 128];
        __syncwarp();
        for (int c = lane; c < NC; c += 32) {
            float acc = 0.f;
#pragma unroll 8
            for (int k = 0; k < HO1; k++) acc += rowbuf[wid][k] * Ws[k * NC + c];
            g_h2[(size_t)row * NC + c] = acc;
        }
    }
}

// ---------------- alpha2: scalar per node ----------------
__global__ void k_alpha2(const float* __restrict__ a_s, const float* __restrict__ a_d) {
    int node = (blockIdx.x * blockDim.x + threadIdx.x) >> 5;
    int lane = threadIdx.x & 31;
    if (node >= NN) return;
    float ps = 0.f, pd = 0.f;
    {
        float h = g_h2[(size_t)node * NC + lane];
        ps += h * a_s[lane];
        pd += h * a_d[lane];
        if (lane < 8) {
            float h2 = g_h2[(size_t)node * NC + 32 + lane];
            ps += h2 * a_s[32 + lane];
            pd += h2 * a_d[32 + lane];
        }
    }
#pragma unroll
    for (int off = 16; off > 0; off >>= 1) {
        ps += __shfl_down_sync(0xffffffff, ps, off);
        pd += __shfl_down_sync(0xffffffff, pd, off);
    }
    if (lane == 0) {
        g_as2[node] = ps;
        g_ad2[node] = pd;
    }
}

// ---------------- aggregation layer 2 -> final output ----------------
__global__ void k_agg2(const float* __restrict__ b2, float* __restrict__ out) {
    int node = blockIdx.x * 8 + (threadIdx.x >> 5);
    int lane = threadIdx.x & 31;
    if (node >= NN) return;
    float ad = g_ad2[node];
    int beg = g_rowptr[node], end = g_rowptr[node + 1];

    float m = -INFINITY;
    for (int e = beg; e < end; e++) {
        float v = g_as2[g_col[e]] + ad;
        v = v > 0.f ? v : NEG_SLOPE * v;
        m = fmaxf(m, v);
    }
    float denom = 0.f, a0 = 0.f, a1 = 0.f;
    for (int e = beg; e < end; e++) {
        int s = g_col[e];
        float v = g_as2[s] + ad;
        v = v > 0.f ? v : NEG_SLOPE * v;
        float ex = __expf(v - m);
        denom += ex;
        float w = ex * g_wcsr[e];
        a0 += w * g_h2[(size_t)s * NC + lane];
        if (lane < 8) a1 += w * g_h2[(size_t)s * NC + 32 + lane];
    }
    float inv = 1.0f / (denom + 1e-16f);
    out[(size_t)node * NC + lane] = a0 * inv + b2[lane];
    if (lane < 8) out[(size_t)node * NC + 32 + lane] = a1 * inv + b2[32 + lane];
}

// ---------------- launch ----------------
extern "C" void kernel_launch(void* const* d_in, const int* in_sizes, int n_in,
                              void* d_out, int out_size) {
    const float* x    = (const float*)d_in[0];
    const int*   ei   = (const int*)  d_in[1];
    const float* ew   = (const float*)d_in[2];
    const float* W1   = (const float*)d_in[3];
    const float* as1  = (const float*)d_in[4];
    const float* ad1  = (const float*)d_in[5];
    const float* b1   = (const float*)d_in[6];
    const float* W2   = (const float*)d_in[7];
    const float* as2w = (const float*)d_in[8];
    const float* ad2w = (const float*)d_in[9];
    const float* b2   = (const float*)d_in[10];
    float* out = (float*)d_out;

    const int* src = ei;
    const int* dst = ei + EE;

    // CSR build (by destination)
    k_deg_init<<<(NN + 255) / 256, 256>>>();
    k_count<<<(EE + 255) / 256, 256>>>(dst);
    k_scan<<<1, 1024>>>();
    k_scatter<<<(EE + 255) / 256, 256>>>(src, dst, ew);
    k_selfloop<<<(NN + 255) / 256, 256>>>();

    // Layer 1
    k_gemm1<<<dim3(HO1 / 128, (NN + 127) / 128), 256>>>(x, W1);
    k_alpha1<<<(NN * HEADS + 7) / 8, 256>>>(as1, ad1);
    k_agg1<<<(NN + 3) / 4, 256>>>(b1);

    // Layer 2
    k_gemm2<<<(NN + 7) / 8, 256>>>(W2);
    k_alpha2<<<(NN + 7) / 8, 256>>>(as2w, ad2w);
    k_agg2<<<(NN + 7) / 8, 256>>>(b2, out);
}

// round 3
// speedup vs baseline: 1.2524x; 1.2524x over previous
#include <cuda_runtime.h>
#include <cuda_bf16.h>
#include <math.h>
#include <stdint.h>

// Problem constants (fixed shapes)
#define NN    50000
#define EE    800000
#define ET    850000          // EE + NN self-loops
#define FIN   512
#define HEADS 4
#define HID   64
#define HO1   256             // HEADS*HID
#define NC    40
#define NEG_SLOPE 0.2f

// ---------------- device scratch (static, no allocations) ----------------
__device__ float g_h1 [(size_t)NN * HO1];   // x@W1
__device__ float g_h1p[(size_t)NN * HO1];   // relu(agg1 + b1)
__device__ float g_h2 [(size_t)NN * NC];    // h1p@W2
__device__ float g_as1[NN * HEADS];
__device__ float g_ad1[NN * HEADS];
__device__ float g_as2[NN];
__device__ float g_ad2[NN];
__device__ int   g_deg[NN];
__device__ int   g_rowptr[NN + 1];
__device__ int   g_cursor[NN];
__device__ int   g_col [ET];
__device__ float g_wcsr[ET];
// bf16 hi/lo split operands for tensor-core GEMM1
__device__ __nv_bfloat16 g_xhi[(size_t)NN * FIN];
__device__ __nv_bfloat16 g_xlo[(size_t)NN * FIN];
__device__ __nv_bfloat16 g_w1h[FIN * HO1];
__device__ __nv_bfloat16 g_w1l[FIN * HO1];

// ---------------- CSR build ----------------
__global__ void k_deg_init() {
    int i = blockIdx.x * blockDim.x + threadIdx.x;
    if (i < NN) g_deg[i] = 1;   // self-loop
}

__global__ void k_count(const int* __restrict__ dst) {
    int e = blockIdx.x * blockDim.x + threadIdx.x;
    if (e < EE) atomicAdd(&g_deg[dst[e]], 1);
}

__global__ void k_scan() {
    __shared__ int partial[1024];
    const int n = NN;
    const int chunk = (n + 1023) / 1024;
    int t = threadIdx.x;
    int beg = t * chunk;
    int end = beg + chunk; if (end > n) end = n;
    int s = 0;
    for (int i = beg; i < end && i < n; i++) s += g_deg[i];
    partial[t] = s;
    __syncthreads();
    for (int off = 1; off < 1024; off <<= 1) {
        int v = (t >= off) ? partial[t - off] : 0;
        __syncthreads();
        partial[t] += v;
        __syncthreads();
    }
    int run = (t == 0) ? 0 : partial[t - 1];
    for (int i = beg; i < end && i < n; i++) {
        g_rowptr[i] = run;
        g_cursor[i] = run;
        run += g_deg[i];
    }
    if (t == 1023) g_rowptr[n] = partial[1023];
}

__global__ void k_scatter(const int* __restrict__ src, const int* __restrict__ dst,
                          const float* __restrict__ ew) {
    int e = blockIdx.x * blockDim.x + threadIdx.x;
    if (e < EE) {
        int d = dst[e];
        int pos = atomicAdd(&g_cursor[d], 1);
        g_col[pos]  = src[e];
        g_wcsr[pos] = ew[e];
    }
}

__global__ void k_selfloop() {
    int i = blockIdx.x * blockDim.x + threadIdx.x;
    if (i < NN) {
        int pos = atomicAdd(&g_cursor[i], 1);
        g_col[pos]  = i;
        g_wcsr[pos] = 1.0f;
    }
}

// ---------------- bf16 hi/lo split ----------------
__device__ __forceinline__ void split4(float4 v, uint2& ph, uint2& pl) {
    float f[4] = {v.x, v.y, v.z, v.w};
    unsigned short h[4], l[4];
#pragma unroll
    for (int j = 0; j < 4; j++) {
        __nv_bfloat16 hb = __float2bfloat16(f[j]);
        float r = f[j] - __bfloat162float(hb);
        __nv_bfloat16 lb = __float2bfloat16(r);
        h[j] = __bfloat16_as_ushort(hb);
        l[j] = __bfloat16_as_ushort(lb);
    }
    ph.x = (unsigned)h[0] | ((unsigned)h[1] << 16);
    ph.y = (unsigned)h[2] | ((unsigned)h[3] << 16);
    pl.x = (unsigned)l[0] | ((unsigned)l[1] << 16);
    pl.y = (unsigned)l[2] | ((unsigned)l[3] << 16);
}

__global__ void k_split_x(const float* __restrict__ x) {
    size_t i = (size_t)blockIdx.x * blockDim.x + threadIdx.x;
    const size_t n4 = (size_t)NN * FIN / 4;
    if (i >= n4) return;
    float4 v = ((const float4*)x)[i];
    uint2 ph, pl;
    split4(v, ph, pl);
    ((uint2*)g_xhi)[i] = ph;
    ((uint2*)g_xlo)[i] = pl;
}

__global__ void k_split_w(const float* __restrict__ w) {
    size_t i = (size_t)blockIdx.x * blockDim.x + threadIdx.x;
    const size_t n4 = (size_t)(FIN * HO1) / 4;
    if (i >= n4) return;
    float4 v = ((const float4*)w)[i];
    uint2 ph, pl;
    split4(v, ph, pl);
    ((uint2*)g_w1h)[i] = ph;
    ((uint2*)g_w1l)[i] = pl;
}

// ---------------- tensor-core GEMM1 ----------------
__device__ __forceinline__ void ldsm_x4(uint32_t* r, const void* p) {
    uint32_t a = (uint32_t)__cvta_generic_to_shared(p);
    asm volatile("ldmatrix.sync.aligned.m8n8.x4.shared.b16 {%0,%1,%2,%3}, [%4];"
                 : "=r"(r[0]), "=r"(r[1]), "=r"(r[2]), "=r"(r[3]) : "r"(a));
}
__device__ __forceinline__ void ldsm_x4_t(uint32_t* r, const void* p) {
    uint32_t a = (uint32_t)__cvta_generic_to_shared(p);
    asm volatile("ldmatrix.sync.aligned.m8n8.x4.trans.shared.b16 {%0,%1,%2,%3}, [%4];"
                 : "=r"(r[0]), "=r"(r[1]), "=r"(r[2]), "=r"(r[3]) : "r"(a));
}
__device__ __forceinline__ void mma16816(float* c, const uint32_t* a, const uint32_t* b) {
    asm volatile("mma.sync.aligned.m16n8k16.row.col.f32.bf16.bf16.f32 "
                 "{%0,%1,%2,%3},{%4,%5,%6,%7},{%8,%9},{%0,%1,%2,%3};"
                 : "+f"(c[0]), "+f"(c[1]), "+f"(c[2]), "+f"(c[3])
                 : "r"(a[0]), "r"(a[1]), "r"(a[2]), "r"(a[3]), "r"(b[0]), "r"(b[1]));
}

// 128x128 block tile, BK=16, 8 warps in 2(m) x 4(n); warp tile 64x32.
// hi/lo split: acc += Ah*Bh + Ah*Bl + Al*Bh  (fp32 accum)
__global__ __launch_bounds__(256, 1) void k_gemm1_mma() {
    __shared__ __nv_bfloat16 sAh[128][24];
    __shared__ __nv_bfloat16 sAl[128][24];
    __shared__ __nv_bfloat16 sBh[16][136];
    __shared__ __nv_bfloat16 sBl[16][136];

    int tid = threadIdx.x;
    int lane = tid & 31;
    int wid = tid >> 5;
    int wm = wid >> 2;           // 0..1
    int wn = wid & 3;            // 0..3
    int rowBase = blockIdx.y * 128;
    int colBase = blockIdx.x * 128;

    // global staging indices
    int arow = tid >> 1;           // 0..127
    int acol = (tid & 1) * 8;      // 0 or 8
    int brow = tid >> 4;           // 0..15
    int bcol = (tid & 15) * 8;     // 0..120

    bool aval = (rowBase + arow) < NN;
    const int4* pAh = (const int4*)&g_xhi[(size_t)(rowBase + arow) * FIN + acol];
    const int4* pAl = (const int4*)&g_xlo[(size_t)(rowBase + arow) * FIN + acol];
    const int4* pBh = (const int4*)&g_w1h[(size_t)brow * HO1 + colBase + bcol];
    const int4* pBl = (const int4*)&g_w1l[(size_t)brow * HO1 + colBase + bcol];

    float acc[4][4][4];
#pragma unroll
    for (int i = 0; i < 4; i++)
#pragma unroll
        for (int j = 0; j < 4; j++)
#pragma unroll
            for (int k = 0; k < 4; k++) acc[i][j][k] = 0.f;

    int4 zero4 = make_int4(0, 0, 0, 0);
    int4 rAh = aval ? pAh[0] : zero4;
    int4 rAl = aval ? pAl[0] : zero4;
    int4 rBh = pBh[0];
    int4 rBl = pBl[0];

    int lrow = lane & 15;
    int lblk = (lane >> 4) * 8;

    for (int k0 = 0; k0 < FIN; k0 += 16) {
        *(int4*)&sAh[arow][acol] = rAh;
        *(int4*)&sAl[arow][acol] = rAl;
        *(int4*)&sBh[brow][bcol] = rBh;
        *(int4*)&sBl[brow][bcol] = rBl;
        __syncthreads();

        if (k0 + 16 < FIN) {
            int koff = (k0 + 16) / 8;            // in int4 units along K for A
            rAh = aval ? pAh[koff] : zero4;
            rAl = aval ? pAl[koff] : zero4;
            size_t bstep = (size_t)(k0 + 16) * (HO1 / 8);   // int4 units
            rBh = pBh[bstep];
            rBl = pBl[bstep];
        }

        uint32_t ah[4][4], al[4][4], bh[4][2], bl[4][2];
#pragma unroll
        for (int mi = 0; mi < 4; mi++) {
            int r = wm * 64 + mi * 16 + lrow;
            ldsm_x4(ah[mi], &sAh[r][lblk]);
            ldsm_x4(al[mi], &sAl[r][lblk]);
        }
#pragma unroll
        for (int p = 0; p < 2; p++) {
            uint32_t t[4];
            ldsm_x4_t(t, &sBh[lrow][wn * 32 + p * 16 + lblk]);
            bh[p * 2][0] = t[0]; bh[p * 2][1] = t[1];
            bh[p * 2 + 1][0] = t[2]; bh[p * 2 + 1][1] = t[3];
            ldsm_x4_t(t, &sBl[lrow][wn * 32 + p * 16 + lblk]);
            bl[p * 2][0] = t[0]; bl[p * 2][1] = t[1];
            bl[p * 2 + 1][0] = t[2]; bl[p * 2 + 1][1] = t[3];
        }

#pragma unroll
        for (int mi = 0; mi < 4; mi++)
#pragma unroll
            for (int nj = 0; nj < 4; nj++) mma16816(acc[mi][nj], ah[mi], bh[nj]);
#pragma unroll
        for (int mi = 0; mi < 4; mi++)
#pragma unroll
            for (int nj = 0; nj < 4; nj++) mma16816(acc[mi][nj], ah[mi], bl[nj]);
#pragma unroll
        for (int mi = 0; mi < 4; mi++)
#pragma unroll
            for (int nj = 0; nj < 4; nj++) mma16816(acc[mi][nj], al[mi], bh[nj]);
        __syncthreads();
    }

    // epilogue
    int g = lane >> 2, tq = lane & 3;
#pragma unroll
    for (int mi = 0; mi < 4; mi++) {
        int r0 = rowBase + wm * 64 + mi * 16 + g;
#pragma unroll
        for (int nj = 0; nj < 4; nj++) {
            int c = colBase + wn * 32 + nj * 8 + tq * 2;
            if (r0 < NN)
                *(float2*)&g_h1[(size_t)r0 * HO1 + c] =
                    make_float2(acc[mi][nj][0], acc[mi][nj][1]);
            if (r0 + 8 < NN)
                *(float2*)&g_h1[(size_t)(r0 + 8) * HO1 + c] =
                    make_float2(acc[mi][nj][2], acc[mi][nj][3]);
        }
    }
}

// ---------------- alpha1 ----------------
__global__ void k_alpha1(const float* __restrict__ a_s, const float* __restrict__ a_d) {
    int gw = (blockIdx.x * blockDim.x + threadIdx.x) >> 5;
    int lane = threadIdx.x & 31;
    if (gw >= NN * HEADS) return;
    int node = gw >> 2;
    int hd = gw & 3;
    const float* hrow = &g_h1[(size_t)node * HO1 + hd * HID];
    float2 hv  = *(const float2*)&hrow[lane * 2];
    float2 asv = *(const float2*)&a_s[hd * HID + lane * 2];
    float2 adv = *(const float2*)&a_d[hd * HID + lane * 2];
    float ps = hv.x * asv.x + hv.y * asv.y;
    float pd = hv.x * adv.x + hv.y * adv.y;
#pragma unroll
    for (int off = 16; off > 0; off >>= 1) {
        ps += __shfl_down_sync(0xffffffff, ps, off);
        pd += __shfl_down_sync(0xffffffff, pd, off);
    }
    if (lane == 0) {
        g_as1[gw] = ps;
        g_ad1[gw] = pd;
    }
}

// ---------------- aggregation layer 1 ----------------
__global__ void k_agg1(const float* __restrict__ b1) {
    int node = blockIdx.x * 4 + (threadIdx.x >> 6);
    int t = threadIdx.x & 63;
    if (node >= NN) return;
    int hd = t >> 4;
    float ad = g_ad1[node * HEADS + hd];
    int beg = g_rowptr[node], end = g_rowptr[node + 1];

    float m = -INFINITY;
    for (int e = beg; e < end; e++) {
        int s = g_col[e];
        float v = g_as1[s * HEADS + hd] + ad;
        v = v > 0.f ? v : NEG_SLOPE * v;
        m = fmaxf(m, v);
    }
    float denom = 0.f;
    float4 acc = make_float4(0.f, 0.f, 0.f, 0.f);
    for (int e = beg; e < end; e++) {
        int s = g_col[e];
        float v = g_as1[s * HEADS + hd] + ad;
        v = v > 0.f ? v : NEG_SLOPE * v;
        float ex = __expf(v - m);
        denom += ex;
        float w = ex * g_wcsr[e];
        float4 hv = *(const float4*)&g_h1[(size_t)s * HO1 + 4 * t];
        acc.x += w * hv.x;
        acc.y += w * hv.y;
        acc.z += w * hv.z;
        acc.w += w * hv.w;
    }
    float inv = 1.0f / (denom + 1e-16f);
    float4 b = *(const float4*)&b1[4 * t];
    float4 o;
    o.x = fmaxf(acc.x * inv + b.x, 0.f);
    o.y = fmaxf(acc.y * inv + b.y, 0.f);
    o.z = fmaxf(acc.z * inv + b.z, 0.f);
    o.w = fmaxf(acc.w * inv + b.w, 0.f);
    *(float4*)&g_h1p[(size_t)node * HO1 + 4 * t] = o;
}

// ---------------- GEMM2 ----------------
__global__ __launch_bounds__(256) void k_gemm2(const float* __restrict__ W2) {
    __shared__ float Ws[HO1 * NC];
    __shared__ float rowbuf[8][HO1];
    int t = threadIdx.x;
    for (int i = t; i < HO1 * NC; i += 256) Ws[i] = W2[i];
    int wid = t >> 5, lane = t & 31;
    int row = blockIdx.x * 8 + wid;
    __syncthreads();
    if (row < NN) {
#pragma unroll
        for (int i = 0; i < 2; i++)
            *(float4*)&rowbuf[wid][lane * 4 + i * 128] =
                *(const float4*)&g_h1p[(size_t)row * HO1 + lane * 4 + i * 128];
        __syncwarp();
        for (int c = lane; c < NC; c += 32) {
            float acc = 0.f;
#pragma unroll 8
            for (int k = 0; k < HO1; k++) acc += rowbuf[wid][k] * Ws[k * NC + c];
            g_h2[(size_t)row * NC + c] = acc;
        }
    }
}

// ---------------- alpha2 ----------------
__global__ void k_alpha2(const float* __restrict__ a_s, const float* __restrict__ a_d) {
    int node = (blockIdx.x * blockDim.x + threadIdx.x) >> 5;
    int lane = threadIdx.x & 31;
    if (node >= NN) return;
    float ps = 0.f, pd = 0.f;
    {
        float h = g_h2[(size_t)node * NC + lane];
        ps += h * a_s[lane];
        pd += h * a_d[lane];
        if (lane < 8) {
            float h2 = g_h2[(size_t)node * NC + 32 + lane];
            ps += h2 * a_s[32 + lane];
            pd += h2 * a_d[32 + lane];
        }
    }
#pragma unroll
    for (int off = 16; off > 0; off >>= 1) {
        ps += __shfl_down_sync(0xffffffff, ps, off);
        pd += __shfl_down_sync(0xffffffff, pd, off);
    }
    if (lane == 0) {
        g_as2[node] = ps;
        g_ad2[node] = pd;
    }
}

// ---------------- aggregation layer 2 ----------------
__global__ void k_agg2(const float* __restrict__ b2, float* __restrict__ out) {
    int node = blockIdx.x * 8 + (threadIdx.x >> 5);
    int lane = threadIdx.x & 31;
    if (node >= NN) return;
    float ad = g_ad2[node];
    int beg = g_rowptr[node], end = g_rowptr[node + 1];

    float m = -INFINITY;
    for (int e = beg; e < end; e++) {
        float v = g_as2[g_col[e]] + ad;
        v = v > 0.f ? v : NEG_SLOPE * v;
        m = fmaxf(m, v);
    }
    float denom = 0.f, a0 = 0.f, a1 = 0.f;
    for (int e = beg; e < end; e++) {
        int s = g_col[e];
        float v = g_as2[s] + ad;
        v = v > 0.f ? v : NEG_SLOPE * v;
        float ex = __expf(v - m);
        denom += ex;
        float w = ex * g_wcsr[e];
        a0 += w * g_h2[(size_t)s * NC + lane];
        if (lane < 8) a1 += w * g_h2[(size_t)s * NC + 32 + lane];
    }
    float inv = 1.0f / (denom + 1e-16f);
    out[(size_t)node * NC + lane] = a0 * inv + b2[lane];
    if (lane < 8) out[(size_t)node * NC + 32 + lane] = a1 * inv + b2[32 + lane];
}

// ---------------- launch ----------------
extern "C" void kernel_launch(void* const* d_in, const int* in_sizes, int n_in,
                              void* d_out, int out_size) {
    const float* x    = (const float*)d_in[0];
    const int*   ei   = (const int*)  d_in[1];
    const float* ew   = (const float*)d_in[2];
    const float* W1   = (const float*)d_in[3];
    const float* as1  = (const float*)d_in[4];
    const float* ad1  = (const float*)d_in[5];
    const float* b1   = (const float*)d_in[6];
    const float* W2   = (const float*)d_in[7];
    const float* as2w = (const float*)d_in[8];
    const float* ad2w = (const float*)d_in[9];
    const float* b2   = (const float*)d_in[10];
    float* out = (float*)d_out;

    const int* src = ei;
    const int* dst = ei + EE;

    // CSR build (by destination)
    k_deg_init<<<(NN + 255) / 256, 256>>>();
    k_count<<<(EE + 255) / 256, 256>>>(dst);
    k_scan<<<1, 1024>>>();
    k_scatter<<<(EE + 255) / 256, 256>>>(src, dst, ew);
    k_selfloop<<<(NN + 255) / 256, 256>>>();

    // bf16 hi/lo splits for tensor-core GEMM1
    {
        size_t n4x = (size_t)NN * FIN / 4;
        k_split_x<<<(unsigned)((n4x + 255) / 256), 256>>>(x);
        size_t n4w = (size_t)(FIN * HO1) / 4;
        k_split_w<<<(unsigned)((n4w + 255) / 256), 256>>>(W1);
    }

    // Layer 1
    k_gemm1_mma<<<dim3(HO1 / 128, (NN + 127) / 128), 256>>>();
    k_alpha1<<<(NN * HEADS + 7) / 8, 256>>>(as1, ad1);
    k_agg1<<<(NN + 3) / 4, 256>>>(b1);

    // Layer 2
    k_gemm2<<<(NN + 7) / 8, 256>>>(W2);
    k_alpha2<<<(NN + 7) / 8, 256>>>(as2w, ad2w);
    k_agg2<<<(NN + 7) / 8, 256>>>(b2, out);
}